// round 16
// baseline (speedup 1.0000x reference)
#include <cuda_runtime.h>
#include <cuda_fp16.h>
#include <math.h>
#include <stdint.h>

#define TSTEPS 5
#define BATCH  128
#define IN0    512
#define HID    1024
#define G4     4096
#define OUTD   32
#define SPLITK 4

#define BM 128
#define BN 128
#define BK 32
#define NTH 256
#define RS 40            // smem row stride in fp16 (32 data + 8 pad)

// Scratch (device globals; no allocations allowed)
__device__ float g_xg0[TSTEPS * BATCH * G4];
__device__ float g_xg1[TSTEPS * BATCH * G4];
__device__ float g_h1 [TSTEPS * BATCH * HID];
__device__ float g_h  [BATCH * HID];
__device__ float g_c  [BATCH * HID];

__device__ __forceinline__ uint32_t smem_u32(const void* p) {
    uint32_t a;
    asm("{ .reg .u64 t; cvta.to.shared.u64 t, %1; cvt.u32.u64 %0, t; }"
        : "=r"(a) : "l"(p));
    return a;
}

#define LDSM_X4(R, addr)                                                     \
    asm volatile("ldmatrix.sync.aligned.m8n8.x4.shared.b16 "                 \
                 "{%0,%1,%2,%3}, [%4];"                                      \
                 : "=r"((R)[0]), "=r"((R)[1]), "=r"((R)[2]), "=r"((R)[3])    \
                 : "r"(addr))
#define LDSM_X2(R, addr)                                                     \
    asm volatile("ldmatrix.sync.aligned.m8n8.x2.shared.b16 {%0,%1}, [%2];"   \
                 : "=r"((R)[0]), "=r"((R)[1]) : "r"(addr))
#define MMA_F16(D, Ar, Br)                                                   \
    asm volatile("mma.sync.aligned.m16n8k16.row.col.f32.f16.f16.f32 "        \
                 "{%0,%1,%2,%3}, {%4,%5,%6,%7}, {%8,%9}, {%0,%1,%2,%3};"     \
                 : "+f"((D)[0]), "+f"((D)[1]), "+f"((D)[2]), "+f"((D)[3])    \
                 : "r"((Ar)[0]), "r"((Ar)[1]), "r"((Ar)[2]), "r"((Ar)[3]),   \
                   "r"((Br)[0]), "r"((Br)[1]))

__device__ __forceinline__ uint16_t to_h16(float f) {
    return __half_as_ushort(__float2half_rn(f));
}
// HW tanh approximation (single MUFU instruction, sm_75+)
__device__ __forceinline__ float tanh_hw(float x) {
    float y;
    asm("tanh.approx.f32 %0, %1;" : "=f"(y) : "f"(x));
    return y;
}
// sigmoid via tanh: sig(x) = 0.5 + 0.5*tanh(x/2)
__device__ __forceinline__ float sig_hw(float x) {
    return fmaf(tanh_hw(0.5f * x), 0.5f, 0.5f);
}

// ---------------------------------------------------------------------------
// Tensor-core GEMM: C[M, N] = A[*,K] @ W[N,K]^T  (+bias | RED-accumulate)
// A and W single fp16; ONE MMA per (mt, nt, k-step).
// doRed=0: plain store with b1+b2 bias. doRed=1: atomicAdd into C (xg slice).
// blockIdx: x = N-tile (128), y = M-tile (128), z = split-K slice.
// ---------------------------------------------------------------------------
__global__ __launch_bounds__(NTH) void hmma_gemm(
    const float* __restrict__ A, const float* __restrict__ W,
    int strideA, int strideW, int ksize,
    const float* __restrict__ b1, const float* __restrict__ b2,
    float* __restrict__ Cbase, int ldc, int doRed)
{
    __shared__ uint16_t sA[BM * RS];
    __shared__ uint16_t sW[BN * RS];

    const int tid  = threadIdx.x;
    const int lane = tid & 31;
    const int warp = tid >> 5;
    const int wm   = warp >> 2;           // 0..1
    const int wn   = warp & 3;            // 0..3
    const int row0 = blockIdx.y * BM;
    const int col0 = blockIdx.x * BN;
    const int kbeg = blockIdx.z * ksize;
    const int nch  = ksize / BK;

    const bool isA = (tid < 128);
    const int  t2  = tid & 127;
    const float* src = isA ? (A + (size_t)row0 * strideA)
                           : (W + (size_t)col0 * strideW);
    const int sstr = isA ? strideA : strideW;
    uint16_t* dst = isA ? sA : sW;

    float4 pf[8];
    const uint32_t bA = smem_u32(sA);
    const uint32_t bW = smem_u32(sW);

    float acc[4][4][4];
#pragma unroll
    for (int i = 0; i < 4; i++)
#pragma unroll
        for (int j = 0; j < 4; j++)
#pragma unroll
            for (int v = 0; v < 4; v++) acc[i][j][v] = 0.f;

    // load chunk 0 into regs
#pragma unroll
    for (int i = 0; i < 8; i++) {
        int idx = t2 + 128 * i;           // 0..1023 float4 slots
        int r = idx >> 3, c4 = idx & 7;
        pf[i] = *(const float4*)(src + (size_t)r * sstr + kbeg + c4 * 4);
    }

    const int rl  = lane & 7;
    const int s8  = (lane >> 3) & 1;
    const int s16 = (lane >> 4) & 1;

    for (int c = 0; c < nch; c++) {
        // store regs -> smem (fp16)
#pragma unroll
        for (int i = 0; i < 8; i++) {
            int idx = t2 + 128 * i;
            int r = idx >> 3, c4 = idx & 7;
            float f[4] = {pf[i].x, pf[i].y, pf[i].z, pf[i].w};
            uint16_t a[4];
#pragma unroll
            for (int j = 0; j < 4; j++) a[j] = to_h16(f[j]);
            *(uint2*)(dst + r * RS + c4 * 4) = *(uint2*)a;
        }
        __syncthreads();

        // prefetch next chunk (overlaps MMA stream)
        if (c + 1 < nch) {
            const int kk = kbeg + (c + 1) * BK;
#pragma unroll
            for (int i = 0; i < 8; i++) {
                int idx = t2 + 128 * i;
                int r = idx >> 3, c4 = idx & 7;
                pf[i] = *(const float4*)(src + (size_t)r * sstr + kk + c4 * 4);
            }
        }

        // compute: 2 k-steps of 16, single MMA each
#pragma unroll
        for (int ks = 0; ks < 2; ks++) {
            const int k0b = (ks * 16 + s8 * 8) * 2;
            const int k0a = (ks * 16 + s16 * 8) * 2;

            uint32_t bw[4][2];
#pragma unroll
            for (int nt = 0; nt < 4; nt++) {
                uint32_t ro = (uint32_t)(wn * 32 + nt * 8 + rl) * (RS * 2) + k0b;
                LDSM_X2(bw[nt], bW + ro);
            }
#pragma unroll
            for (int mt = 0; mt < 4; mt++) {
                uint32_t ro = (uint32_t)(wm * 64 + mt * 16 + rl + s8 * 8) * (RS * 2) + k0a;
                uint32_t ah[4];
                LDSM_X4(ah, bA + ro);
#pragma unroll
                for (int nt = 0; nt < 4; nt++) MMA_F16(acc[mt][nt], ah, bw[nt]);
            }
        }
        __syncthreads();
    }

    // Epilogue
    if (doRed) {
        // accumulate into xg slice (split-K reduction in place)
#pragma unroll
        for (int mt = 0; mt < 4; mt++) {
            int row = row0 + wm * 64 + mt * 16 + (lane >> 2);
#pragma unroll
            for (int nt = 0; nt < 4; nt++) {
                int col = col0 + wn * 32 + nt * 8 + (lane & 3) * 2;
                float* p0 = Cbase + (size_t)row * ldc + col;
                float* p1 = Cbase + (size_t)(row + 8) * ldc + col;
                atomicAdd(p0,     acc[mt][nt][0]);
                atomicAdd(p0 + 1, acc[mt][nt][1]);
                atomicAdd(p1,     acc[mt][nt][2]);
                atomicAdd(p1 + 1, acc[mt][nt][3]);
            }
        }
    } else {
#pragma unroll
        for (int mt = 0; mt < 4; mt++) {
            int row = row0 + wm * 64 + mt * 16 + (lane >> 2);
#pragma unroll
            for (int nt = 0; nt < 4; nt++) {
                int col = col0 + wn * 32 + nt * 8 + (lane & 3) * 2;
                float bb0 = b1[col] + b2[col];
                float bb1 = b1[col + 1] + b2[col + 1];
                float2 v0 = make_float2(acc[mt][nt][0] + bb0, acc[mt][nt][1] + bb1);
                float2 v1 = make_float2(acc[mt][nt][2] + bb0, acc[mt][nt][3] + bb1);
                *(float2*)(Cbase + (size_t)row * ldc + col) = v0;
                *(float2*)(Cbase + (size_t)(row + 8) * ldc + col) = v1;
            }
        }
    }
}

// ---------------------------------------------------------------------------
// Gate fusion: xg slice now holds the COMPLETE pre-activation.
// One unit per thread; 5 loads + 3 stores.
// ---------------------------------------------------------------------------
__global__ __launch_bounds__(256) void gates_kernel(
    const float* __restrict__ xg, float* __restrict__ hseq, int first)
{
    int q = blockIdx.x * 256 + threadIdx.x;   // 0..BATCH*HID-1
    int b = q >> 10;
    int j = q & 1023;
    size_t base = (size_t)b * G4 + j;

    float gi = xg[base];
    float gf = xg[base + HID];
    float gg = xg[base + 2 * HID];
    float go = xg[base + 3 * HID];

    int idx = b * HID + j;
    float cp = first ? 0.f : g_c[idx];
    float cn = sig_hw(gf) * cp + sig_hw(gi) * tanh_hw(gg);
    float hn = sig_hw(go) * tanh_hw(cn);
    g_c[idx] = cn;
    g_h[idx] = hn;
    if (hseq) hseq[idx] = hn;
}

// ---------------------------------------------------------------------------
// Head: out[b,o] = dot(h_final[b,:], Wout[o,:]) + bout[o]
// ---------------------------------------------------------------------------
__global__ __launch_bounds__(256) void head_kernel(
    const float* __restrict__ Wout, const float* __restrict__ bout,
    float* __restrict__ out)
{
    __shared__ float hs[HID];
    __shared__ float red[8][32];
    int b = blockIdx.x;
    for (int i = threadIdx.x; i < HID; i += 256) hs[i] = g_h[(size_t)b * HID + i];
    __syncthreads();

    int o     = threadIdx.x % 32;
    int chunk = threadIdx.x / 32;
    float s = 0.f;
    const float* wrow = Wout + (size_t)o * HID;
#pragma unroll 4
    for (int k = chunk * 128; k < chunk * 128 + 128; k++)
        s = fmaf(hs[k], wrow[k], s);
    red[chunk][o] = s;
    __syncthreads();

    if (threadIdx.x < 32) {
        float t = 0.f;
#pragma unroll
        for (int ch = 0; ch < 8; ch++) t += red[ch][threadIdx.x];
        out[(size_t)b * OUTD + threadIdx.x] = t + bout[threadIdx.x];
    }
}

// ---------------------------------------------------------------------------
// Host launcher
// ---------------------------------------------------------------------------
extern "C" void kernel_launch(void* const* d_in, const int* in_sizes, int n_in,
                              void* d_out, int out_size)
{
    const float* input = (const float*)d_in[0];
    const float* w_ih0 = (const float*)d_in[1];
    const float* w_hh0 = (const float*)d_in[2];
    const float* b_ih0 = (const float*)d_in[3];
    const float* b_hh0 = (const float*)d_in[4];
    const float* w_ih1 = (const float*)d_in[5];
    const float* w_hh1 = (const float*)d_in[6];
    const float* b_ih1 = (const float*)d_in[7];
    const float* b_hh1 = (const float*)d_in[8];
    const float* w_out = (const float*)d_in[9];
    const float* b_out = (const float*)d_in[10];
    float* out = (float*)d_out;

    float *xg0, *xg1, *h1, *h;
    cudaGetSymbolAddress((void**)&xg0, g_xg0);
    cudaGetSymbolAddress((void**)&xg1, g_xg1);
    cudaGetSymbolAddress((void**)&h1,  g_h1);
    cudaGetSymbolAddress((void**)&h,   g_h);

    const int KSLICE = HID / SPLITK;   // 256
    const size_t BG  = (size_t)BATCH * G4;

    // 1) Layer-0 input gates: [640,4096] = input[0:640,512] @ w_ih0^T + biases
    {
        dim3 grid(G4 / BN, TSTEPS * BATCH / BM, 1);
        hmma_gemm<<<grid, NTH>>>(input, w_ih0, IN0, IN0, IN0,
                                 b_ih0, b_hh0, xg0, G4, 0);
    }
    // 2) Layer-0 recurrence: step GEMM REDs into xg slice, gates reads it
    for (int t = 0; t < TSTEPS; t++) {
        if (t > 0) {
            dim3 grid(G4 / BN, 1, SPLITK);
            hmma_gemm<<<grid, NTH>>>(h, w_hh0, HID, HID, KSLICE,
                                     (const float*)0, (const float*)0,
                                     xg0 + (size_t)t * BG, G4, 1);
        }
        gates_kernel<<<(BATCH * HID) / 256, 256>>>(
            xg0 + (size_t)t * BG, h1 + (size_t)t * BATCH * HID, t == 0);
    }
    // 3) Layer-1 input gates: [640,4096] = h1 @ w_ih1^T + biases
    {
        dim3 grid(G4 / BN, TSTEPS * BATCH / BM, 1);
        hmma_gemm<<<grid, NTH>>>(h1, w_ih1, HID, HID, HID,
                                 b_ih1, b_hh1, xg1, G4, 0);
    }
    // 4) Layer-1 recurrence
    for (int t = 0; t < TSTEPS; t++) {
        if (t > 0) {
            dim3 grid(G4 / BN, 1, SPLITK);
            hmma_gemm<<<grid, NTH>>>(h, w_hh1, HID, HID, KSLICE,
                                     (const float*)0, (const float*)0,
                                     xg1 + (size_t)t * BG, G4, 1);
        }
        gates_kernel<<<(BATCH * HID) / 256, 256>>>(
            xg1 + (size_t)t * BG, (float*)0, t == 0);
    }
    // 5) Linear head on h2[4]
    head_kernel<<<BATCH, 256>>>(w_out, b_out, out);
}